// round 8
// baseline (speedup 1.0000x reference)
#include <cuda_runtime.h>
#include <cuda_bf16.h>

#define NN 4096
#define MM 512
#define DD 32
#define NBLK 128        // 32 rows per block
#define NT   1024       // 32 warps; each warp owns 16 m-columns x 32 rows

typedef unsigned long long ull;

// sm_103a packed fp32 FMA (FFMA2). Element 0 = low 32 bits.
__device__ __forceinline__ ull ffma2(ull a, ull b, ull c) {
    ull d;
    asm("fma.rn.f32x2 %0, %1, %2, %3;" : "=l"(d) : "l"(a), "l"(b), "l"(c));
    return d;
}
__device__ __forceinline__ float flo(ull v) { return __uint_as_float((unsigned)v); }
__device__ __forceinline__ float fhi(ull v) { return __uint_as_float((unsigned)(v >> 32)); }
__device__ __forceinline__ float sqrt_approx(float v) {
    float r;
    asm("sqrt.approx.f32 %0, %1;" : "=f"(r) : "f"(v));
    return r;
}
__device__ __forceinline__ void cp_async16(unsigned dst, const void* src) {
    asm volatile("cp.async.cg.shared.global [%0], [%1], 16;" :: "r"(dst), "l"(src) : "memory");
}

// ---- smem layout (floats) --------------------------------------------------
#define YS_OFF   0                        // y   [512][32] linear       16384
#define RS_OFF   16384                    // r   private [1024][20]     20480 (80B slots, 64B used)
#define XS_OFF   (RS_OFF + 20480)         // x   [32][36] padded         1152
#define YN2_OFF  (XS_OFF + 1152)          // |y|^2 [512]                  512
#define XN2_OFF  (YN2_OFF + 512)          // |x|^2 [32]                    32
#define PART_OFF (XN2_OFF + 32)           // warp partials [3][32][32]   3072
#define SMEM_FLOATS (PART_OFF + 3072)
#define SMEM_BYTES  (SMEM_FLOATS * 4)     // 166528 B

// ---------------------------------------------------------------------------
// Single fused kernel, 32 Sinkhorn rows per block.
//  y,x staged coalesced (|.|^2 via 8-lane shfl reductions, one barrier total);
//  r staged per-thread-private via cp.async (each thread copies exactly the
//  64B it later reads -> no barrier, overlapped with the dot computation).
//  d-packed f32x2 dot products; C = sqrt(|x|^2+|y|^2-2x.y); K = exp(-C/2);
//  warp partials -> warp 0 runs the scalar u-recurrence with block-local
//  early stop; out[n] = u*T/(u+1e-8).
// ---------------------------------------------------------------------------
__global__ __launch_bounds__(NT) void sinkhorn_fused_kernel(
    const float* __restrict__ x,   // [NN, DD]
    const float* __restrict__ y,   // [MM, DD]
    const float* __restrict__ r,   // [NN, MM]
    float* __restrict__ out)       // [NN]
{
    extern __shared__ float sm[];
    float4* ys4  = (float4*)(sm + YS_OFF);
    float4* rp4  = (float4*)(sm + RS_OFF);   // slot stride 5 float4 (80B)
    float4* xs4  = (float4*)(sm + XS_OFF);
    float*  yn2  = sm + YN2_OFF;
    float*  xn2s = sm + XN2_OFF;
    float*  part = sm + PART_OFF;

    const int tid  = threadIdx.x;
    const int warp = tid >> 5;
    const int lane = tid & 31;
    const int nb   = blockIdx.x << 5;
    const int mc   = warp << 4;              // this warp's 16-column m-chunk

    const unsigned rp_base =
        (unsigned)__cvta_generic_to_shared(rp4 + (size_t)tid * 5);

    // ---- y staging: coalesced LDG.128, 4 per thread (issued first) ---------
    const float4* yg4 = (const float4*)y;    // 4096 float4
    float4 ya[4];
#pragma unroll
    for (int k = 0; k < 4; k++) ya[k] = yg4[tid + 1024 * k];

    // ---- r: 4x cp.async.cg 16B, thread-private (this thread's own 64B) -----
    {
        const float* rsrc = r + (size_t)(nb + lane) * MM + mc;
#pragma unroll
        for (int j = 0; j < 4; j++)
            cp_async16(rp_base + 16u * j, rsrc + 4 * j);
        asm volatile("cp.async.commit_group;" ::: "memory");
    }

    // ---- x staging (tid<256): padded copy + |x|^2 via 8-lane shfl ----------
    if (tid < 256) {
        int m = tid >> 3, slot = tid & 7;
        float4 a = ((const float4*)x)[(nb + m) * 8 + slot];
        xs4[m * 9 + slot] = a;
        float sq = fmaf(a.x, a.x, fmaf(a.y, a.y, fmaf(a.z, a.z, a.w * a.w)));
        sq += __shfl_xor_sync(0xffffffffu, sq, 1);
        sq += __shfl_xor_sync(0xffffffffu, sq, 2);
        sq += __shfl_xor_sync(0xffffffffu, sq, 4);
        if (slot == 0) xn2s[m] = sq;
    }

    // ---- y: store + |y|^2 via 8-lane shfl (8 consecutive tids per m) -------
#pragma unroll
    for (int k = 0; k < 4; k++) {
        int idx = tid + 1024 * k;
        float4 a = ya[k];
        ys4[idx] = a;
        float sq = fmaf(a.x, a.x, fmaf(a.y, a.y, fmaf(a.z, a.z, a.w * a.w)));
        sq += __shfl_xor_sync(0xffffffffu, sq, 1);
        sq += __shfl_xor_sync(0xffffffffu, sq, 2);
        sq += __shfl_xor_sync(0xffffffffu, sq, 4);
        if ((idx & 7) == 0) yn2[idx >> 3] = sq;
    }
    __syncthreads();   // y, yn2, xs, xn2s visible (r is private-async)

    // ---- main: lane owns row n = nb+lane; 2 m-tiles of 8 -------------------
    const float xn2 = xn2s[lane];
    float Racc = 0.f, Sacc = 0.f, Tacc = 0.f;

    const ulonglong2* ys2 = (const ulonglong2*)ys4;
    const ulonglong2* xs2 = (const ulonglong2*)xs4;

#pragma unroll
    for (int mt = 0; mt < 2; mt++) {
        const int mb = mc + (mt << 3);       // m-tile of 8
        ull A[8] = {0, 0, 0, 0, 0, 0, 0, 0};
#pragma unroll
        for (int p2 = 0; p2 < 8; p2++) {     // 4 d's per step (2 packed pairs)
            ulonglong2 xp = xs2[lane * 9 + p2];          // conflict-free
#pragma unroll
            for (int j = 0; j < 8; j++) {
                ulonglong2 yp = ys2[(mb + j) * 8 + p2];  // broadcast LDS.128
                A[j] = ffma2(xp.x, yp.x, A[j]);
                A[j] = ffma2(xp.y, yp.y, A[j]);
            }
        }
        if (mt == 0)   // r landed during the dot loop
            asm volatile("cp.async.wait_group 0;" ::: "memory");

        float4 r4a = rp4[(size_t)tid * 5 + 2 * mt];      // private, cf banks
        float4 r4b = rp4[(size_t)tid * 5 + 2 * mt + 1];
        float rv[8] = { r4a.x, r4a.y, r4a.z, r4a.w, r4b.x, r4b.y, r4b.z, r4b.w };
#pragma unroll
        for (int j = 0; j < 8; j++) {
            float dot = flo(A[j]) + fhi(A[j]);
            float d2  = fmaf(-2.f, dot, xn2 + yn2[mb + j]);
            float C   = sqrt_approx(fmaxf(d2, 0.f));
            float K   = exp2f(C * -0.72134752f);         // exp(-C/2)
            Racc += K;
            float Kr = K * rv[j];
            Sacc += Kr;
            Tacc = fmaf(Kr, C, Tacc);
        }
    }

    // ---- combine 32 warp partials in fixed order (deterministic) -----------
    part[(0 * 32 + warp) * 32 + lane] = Racc;
    part[(1 * 32 + warp) * 32 + lane] = Sacc;
    part[(2 * 32 + warp) * 32 + lane] = Tacc;
    __syncthreads();

    if (warp == 0) {
        float R = 0.f, S = 0.f, T = 0.f;
#pragma unroll
        for (int w = 0; w < 32; w++) {
            R += part[(0 * 32 + w) * 32 + lane];
            S += part[(1 * 32 + w) * 32 + lane];
            T += part[(2 * 32 + w) * 32 + lane];
        }

        // Scalar Sinkhorn recurrence, block-local early stop:
        //   iter 1:   u = 1/(R + 1e-8)
        //   iter t>1: u = 1/(S/(u+1e-8) + 1e-8)
        //   stop once mean_32 |u_new - u| < 0.1 (after applying update)
        float u = 1.f;
        bool done = false;
        for (int t = 0; t < 100 && !done; t++) {
            float denom = (t == 0) ? R : (S / (u + 1e-8f));
            float un = 1.f / (denom + 1e-8f);
            float e = fabsf(un - u);
            u = un;
#pragma unroll
            for (int off = 16; off > 0; off >>= 1)
                e += __shfl_xor_sync(0xffffffffu, e, off);
            done = (e < 0.1f * 32.f);        // uniform across warp
        }
        out[nb + lane] = u * T / (u + 1e-8f);
    }
}

extern "C" void kernel_launch(void* const* d_in, const int* in_sizes, int n_in,
                              void* d_out, int out_size)
{
    const float* x = (const float*)d_in[0];  // [4096, 32]
    const float* y = (const float*)d_in[1];  // [512, 32]
    const float* r = (const float*)d_in[2];  // [4096, 512]
    float* out = (float*)d_out;              // [4096]

    cudaFuncSetAttribute(sinkhorn_fused_kernel,
                         cudaFuncAttributeMaxDynamicSharedMemorySize, SMEM_BYTES);
    sinkhorn_fused_kernel<<<NBLK, NT, SMEM_BYTES>>>(x, y, r, out);
}